// round 14
// baseline (speedup 1.0000x reference)
#include <cuda_runtime.h>
#include <math.h>
#include <stdint.h>

#define NEL 32
#define NUP 16
#define NI  32
#define NL  16
#define NK  16
#define H1  128
#define H2  4
#define FLEN 392
#define GRID 128

// ---- device-global state (no allocation allowed) ----
__device__ float g_sh[2][NEL][H1];
__device__ float g_rN[NEL][NI];
__device__ float g_phi[NK][2][16][16];
__device__ float g_det[NK][2];
__device__ unsigned g_bar[NL + 2];

// ---------------- R2's barrier, verbatim ----------------
__device__ __forceinline__ unsigned ld_acq(const unsigned* p) {
    unsigned v;
    asm volatile("ld.acquire.gpu.global.u32 %0, [%1];" : "=r"(v) : "l"(p) : "memory");
    return v;
}
__device__ __forceinline__ void red_rel_add1(unsigned* p) {
    asm volatile("red.release.gpu.global.add.u32 [%0], 1;" :: "l"(p) : "memory");
}
__device__ __forceinline__ void bar_arrive(int idx) {
    __syncthreads();
    if (threadIdx.x == 0) red_rel_add1(&g_bar[idx]);
}
__device__ __forceinline__ void bar_wait(int idx, unsigned target) {
    if (threadIdx.x == 0) {
        while (ld_acq(&g_bar[idx]) < target) { }
    }
    __syncthreads();
}

// ---------------- cluster / DSMEM helpers ----------------
__device__ __forceinline__ void cluster_arrive() {
    asm volatile("barrier.cluster.arrive.aligned;" ::: "memory");
}
__device__ __forceinline__ void cluster_wait() {
    asm volatile("barrier.cluster.wait.aligned;" ::: "memory");
}
__device__ __forceinline__ uint32_t mapa_addr(uint32_t saddr, int rank) {
    uint32_t r;
    asm("mapa.shared::cluster.u32 %0, %1, %2;" : "=r"(r) : "r"(saddr), "r"(rank));
    return r;
}
__device__ __forceinline__ void st_dsm(uint32_t saddr, float v) {
    asm volatile("st.shared::cluster.f32 [%0], %1;" :: "r"(saddr), "f"(v) : "memory");
}

// ---------------------------------------------------------------------------
// Preprocess: sh^0 + rN + zero counters (every replay)
// ---------------------------------------------------------------------------
__global__ void pre_kernel(const float* __restrict__ ep,
                           const float* __restrict__ nuc) {
    int t = threadIdx.x;
    if (t < NL + 2) g_bar[t] = 0;
    for (int p = t; p < NEL * NI; p += blockDim.x) {
        int j = p >> 5, m = p & 31;
        float dx = ep[j * 3 + 0] - nuc[m * 3 + 0];
        float dy = ep[j * 3 + 1] - nuc[m * 3 + 1];
        float dz = ep[j * 3 + 2] - nuc[m * 3 + 2];
        float r  = sqrtf(dx * dx + dy * dy + dz * dz);
        g_sh[0][j][m * 3 + 0] = dx;
        g_sh[0][j][m * 3 + 1] = dy;
        g_sh[0][j][m * 3 + 2] = dz;
        g_sh[0][j][3 * NI + m] = r;
        g_rN[j][m] = r;
    }
}

// ---------------------------------------------------------------------------
// Fused persistent kernel — R11 compute, byte-identical, + freq probe at end.
// ---------------------------------------------------------------------------
__global__ void __launch_bounds__(256, 1) __cluster_dims__(4, 1, 1) fused_kernel(
    const float* __restrict__ ep, const float* __restrict__ nuc,
    const float* __restrict__ v,
    const float* __restrict__ b,  const float* __restrict__ w,
    const float* __restrict__ c,  const float* __restrict__ fw,
    const float* __restrict__ fb, const float* __restrict__ pi,
    const float* __restrict__ sigma, const float* __restrict__ omega,
    float* __restrict__ out)
{
    __shared__ float m_s[256];
    __shared__ float sh_loc[2][H1];
    __shared__ float pd[2][4][4];
    __shared__ float dg_s[8];
    __shared__ float part_s[8][33];
    __shared__ float A[16][17];
    __shared__ float fac[16];
    __shared__ int   pivs;
    __shared__ float dsh;

    const int t    = threadIdx.x;
    const int n    = blockIdx.x >> 2;
    const int og   = blockIdx.x & 3;
    const int c4   = t & 7;
    const int fs   = t >> 3;
    const int lane = t & 31, wrp = t >> 5;
    const int dj   = og * 8 + t;

    const uint32_t shloc_s = (uint32_t)__cvta_generic_to_shared(&sh_loc[0][0]);
    const uint32_t pd_s    = (uint32_t)__cvta_generic_to_shared(&pd[0][0][0]);

    // ---------------- prologue: local sh^0, dh^0 + partials ----------------
    if (t < H1) {
        float val;
        if (t < 96) {
            int m = t / 3, cp = t % 3;
            val = ep[n * 3 + cp] - nuc[m * 3 + cp];
        } else {
            int m = t - 96;
            float dx = ep[n * 3 + 0] - nuc[m * 3 + 0];
            float dy = ep[n * 3 + 1] - nuc[m * 3 + 1];
            float dz = ep[n * 3 + 2] - nuc[m * 3 + 2];
            val = sqrtf(dx * dx + dy * dy + dz * dz);
        }
        sh_loc[0][t] = val;
    }
    float4 d4;
    if (t < 8) {
        float dx = ep[n * 3 + 0] - ep[dj * 3 + 0];
        float dy = ep[n * 3 + 1] - ep[dj * 3 + 1];
        float dz = ep[n * 3 + 2] - ep[dj * 3 + 2];
        d4 = make_float4(dx, dy, dz, sqrtf(dx * dx + dy * dy + dz * dz));
        float4 s = d4;
        s.x += __shfl_down_sync(0xffu, s.x, 4, 8);
        s.y += __shfl_down_sync(0xffu, s.y, 4, 8);
        s.z += __shfl_down_sync(0xffu, s.z, 4, 8);
        s.w += __shfl_down_sync(0xffu, s.w, 4, 8);
        s.x += __shfl_down_sync(0xffu, s.x, 2, 8);
        s.y += __shfl_down_sync(0xffu, s.y, 2, 8);
        s.z += __shfl_down_sync(0xffu, s.z, 2, 8);
        s.w += __shfl_down_sync(0xffu, s.w, 2, 8);
        s.x += __shfl_down_sync(0xffu, s.x, 1, 8);
        s.y += __shfl_down_sync(0xffu, s.y, 1, 8);
        s.z += __shfl_down_sync(0xffu, s.z, 1, 8);
        s.w += __shfl_down_sync(0xffu, s.w, 1, 8);
        if (t == 0) {
            uint32_t base = pd_s + (0 * 4 + og) * 16;
            for (int rk = 0; rk < 4; rk++) {
                uint32_t ra = mapa_addr(base, rk);
                st_dsm(ra + 0,  s.x);
                st_dsm(ra + 4,  s.y);
                st_dsm(ra + 8,  s.z);
                st_dsm(ra + 12, s.w);
            }
        }
    }
    cluster_arrive();

    float4 wr[13];
    float4 dw0, dw1, dw2, dw3, dc4;

#pragma unroll 1
    for (int l = 0; l < NL; l++) {
        const int p   = l & 1;
        const int cur = l & 1, nxt = cur ^ 1;

        {
            const float* vp = v + (((size_t)l * NEL + n) * FLEN) * H1 + og * 32 + c4 * 4;
#pragma unroll
            for (int i = 0; i < 12; i++)
                wr[i] = *reinterpret_cast<const float4*>(vp + (size_t)(fs + 32 * i) * H1);
            if (fs < 8)
                wr[12] = *reinterpret_cast<const float4*>(vp + (size_t)(fs + 384) * H1);
        }
        float bias_r = 0.f;
        if (t < 32) bias_r = b[((size_t)l * NEL + n) * H1 + og * 32 + t];
        const bool do_d = (t < 8) && (l < NL - 1);
        if (do_d) {
            const float* wp = w + ((size_t)(l * NEL + n) * NEL + dj) * 16;
            dw0 = *reinterpret_cast<const float4*>(wp);
            dw1 = *reinterpret_cast<const float4*>(wp + 4);
            dw2 = *reinterpret_cast<const float4*>(wp + 8);
            dw3 = *reinterpret_cast<const float4*>(wp + 12);
            dc4 = *reinterpret_cast<const float4*>(
                c + ((size_t)(l * NEL + n) * NEL + dj) * 4);
        }

        cluster_wait();
        if (t < 8) {
            int d = t & 3;
            float a = (t < 4) ? (pd[p][0][d] + pd[p][1][d])
                              : (pd[p][2][d] + pd[p][3][d]);
            dg_s[t] = a * (1.0f / 16);
        }
        __syncthreads();

        float4 acc = make_float4(0.f, 0.f, 0.f, 0.f);
#pragma unroll
        for (int i = 0; i < 4; i++) {
            float s = sh_loc[p][fs + 32 * i];
            acc.x += s * wr[i].x; acc.y += s * wr[i].y;
            acc.z += s * wr[i].z; acc.w += s * wr[i].w;
        }
        if (fs < 8) {
            float s = dg_s[fs];
            acc.x += s * wr[12].x; acc.y += s * wr[12].y;
            acc.z += s * wr[12].z; acc.w += s * wr[12].w;
        }

        float4 od;
        if (do_d) {
            float o0 = d4.x * dw0.x + d4.y * dw1.x + d4.z * dw2.x + d4.w * dw3.x;
            float o1 = d4.x * dw0.y + d4.y * dw1.y + d4.z * dw2.y + d4.w * dw3.y;
            float o2 = d4.x * dw0.z + d4.y * dw1.z + d4.z * dw2.z + d4.w * dw3.z;
            float o3 = d4.x * dw0.w + d4.y * dw1.w + d4.z * dw2.w + d4.w * dw3.w;
            od.x = tanhf(o0 + dc4.x) + d4.x;
            od.y = tanhf(o1 + dc4.y) + d4.y;
            od.z = tanhf(o2 + dc4.z) + d4.z;
            od.w = tanhf(o3 + dc4.w) + d4.w;
        }

        if (l > 0) bar_wait(l - 1, GRID);

        if (t < 128) {
            float s = 0.f;
#pragma unroll
            for (int r = 0; r < NUP; r++) s += __ldcg(&g_sh[cur][r][t]);
            m_s[t] = s * (1.0f / 16);
        } else {
            int o = t - 128;
            float s = 0.f;
#pragma unroll
            for (int r = NUP; r < NEL; r++) s += __ldcg(&g_sh[cur][r][o]);
            m_s[128 + o] = s * (1.0f / 16);
        }
        __syncthreads();

#pragma unroll
        for (int q = 0; q < 8; q++) {
            float s = m_s[fs + 32 * q];
            acc.x += s * wr[4 + q].x; acc.y += s * wr[4 + q].y;
            acc.z += s * wr[4 + q].z; acc.w += s * wr[4 + q].w;
        }

#pragma unroll
        for (int off = 16; off >= 8; off >>= 1) {
            acc.x += __shfl_down_sync(0xffffffffu, acc.x, off);
            acc.y += __shfl_down_sync(0xffffffffu, acc.y, off);
            acc.z += __shfl_down_sync(0xffffffffu, acc.z, off);
            acc.w += __shfl_down_sync(0xffffffffu, acc.w, off);
        }
        if (lane < 8) {
            part_s[wrp][lane * 4 + 0] = acc.x;
            part_s[wrp][lane * 4 + 1] = acc.y;
            part_s[wrp][lane * 4 + 2] = acc.z;
            part_s[wrp][lane * 4 + 3] = acc.w;
        }
        __syncthreads();

        if (t < 32) {
            float a = part_s[0][t];
#pragma unroll
            for (int ww = 1; ww < 8; ww++) a += part_s[ww][t];
            int o = og * 32 + t;
            float val = tanhf(a + bias_r) + sh_loc[p][o];
            __stcg(&g_sh[nxt][n][o], val);
            if (l < NL - 1) {
                uint32_t base = shloc_s + ((p ^ 1) * H1 + o) * 4;
#pragma unroll
                for (int rk = 0; rk < 4; rk++)
                    st_dsm(mapa_addr(base, rk), val);
            }
        }

        if (do_d) {
            d4 = od;
            float4 s = d4;
            s.x += __shfl_down_sync(0xffu, s.x, 4, 8);
            s.y += __shfl_down_sync(0xffu, s.y, 4, 8);
            s.z += __shfl_down_sync(0xffu, s.z, 4, 8);
            s.w += __shfl_down_sync(0xffu, s.w, 4, 8);
            s.x += __shfl_down_sync(0xffu, s.x, 2, 8);
            s.y += __shfl_down_sync(0xffu, s.y, 2, 8);
            s.z += __shfl_down_sync(0xffu, s.z, 2, 8);
            s.w += __shfl_down_sync(0xffu, s.w, 2, 8);
            s.x += __shfl_down_sync(0xffu, s.x, 1, 8);
            s.y += __shfl_down_sync(0xffu, s.y, 1, 8);
            s.z += __shfl_down_sync(0xffu, s.z, 1, 8);
            s.w += __shfl_down_sync(0xffu, s.w, 1, 8);
            if (t == 0) {
                uint32_t base = pd_s + (((p ^ 1) * 4 + og) * 4) * 4;
                for (int rk = 0; rk < 4; rk++) {
                    uint32_t ra = mapa_addr(base, rk);
                    st_dsm(ra + 0,  s.x);
                    st_dsm(ra + 4,  s.y);
                    st_dsm(ra + 8,  s.z);
                    st_dsm(ra + 12, s.w);
                }
            }
        }
        if (l < NL - 1) cluster_arrive();
        bar_arrive(l);
    }

    // ================= phi =================
    bar_wait(NL - 1, GRID);
    {
        const int k    = blockIdx.x >> 3;
        const int i    = (blockIdx.x & 7) * 4 + (t >> 6);
        const int spin = i >> 4;
        const int tl   = t & 63;
        const int jl   = tl >> 2, s = tl & 3;
        const int j    = spin * 16 + jl;
        const float* fwp = fw + (size_t)(k * NEL + i) * H1;
        float dot = 0.f;
#pragma unroll
        for (int q = 0; q < 32; q++)
            dot += fwp[s + 4 * q] * __ldcg(&g_sh[0][j][s + 4 * q]);
        const float* pip = pi    + (size_t)(k * NEL + i) * NI;
        const float* sgp = sigma + (size_t)(k * NEL + i) * NI;
        float env = 0.f;
#pragma unroll
        for (int q = 0; q < 8; q++) {
            int m = s * 8 + q;
            env += pip[m] * __expf(-fabsf(sgp[m]) * g_rN[j][m]);
        }
        dot += __shfl_down_sync(0xffffffffu, dot, 2, 4);
        dot += __shfl_down_sync(0xffffffffu, dot, 1, 4);
        env += __shfl_down_sync(0xffffffffu, env, 2, 4);
        env += __shfl_down_sync(0xffffffffu, env, 1, 4);
        if (s == 0)
            __stcg(&g_phi[k][spin][i & 15][jl], (dot + fb[k * NEL + i]) * env);
    }
    bar_arrive(NL);

    // ================= determinants (blocks 0..31) =================
    if (blockIdx.x < 32) {
        bar_wait(NL, GRID);
        const int k = blockIdx.x >> 1, spin = blockIdx.x & 1;
        const int r = t >> 4, cc = t & 15;
        A[r][cc] = __ldcg(&g_phi[k][spin][r][cc]);
        if (t == 0) dsh = 1.0f;
        __syncthreads();
        for (int pp = 0; pp < 16; pp++) {
            if (t == 0) {
                int best = pp;
                float bv = fabsf(A[pp][pp]);
                for (int rr = pp + 1; rr < 16; rr++) {
                    float v2 = fabsf(A[rr][pp]);
                    if (v2 > bv) { bv = v2; best = rr; }
                }
                pivs = best;
                if (best != pp) dsh = -dsh;
            }
            __syncthreads();
            int piv = pivs;
            if (piv != pp && t < 16) {
                float tmp = A[pp][t]; A[pp][t] = A[piv][t]; A[piv][t] = tmp;
            }
            __syncthreads();
            if (t < 16 && t > pp) fac[t] = A[t][pp] / A[pp][pp];
            if (t == 0) dsh *= A[pp][pp];
            __syncthreads();
            if (r > pp && cc > pp) A[r][cc] -= fac[r] * A[pp][cc];
            __syncthreads();
        }
        if (t == 0) __stcg(&g_det[k][spin], dsh);
        bar_arrive(NL + 1);
    }

    // ================= final reduction (block 0) + FREQ PROBE =================
    if (blockIdx.x == 0) {
        bar_wait(NL + 1, 32);
        if (t < 32) {
            float vv = (t < NK) ? omega[t] * __ldcg(&g_det[t][0]) * __ldcg(&g_det[t][1])
                                : 0.0f;
#pragma unroll
            for (int off = 16; off; off >>= 1)
                vv += __shfl_down_sync(0xffffffffu, vv, off);
            if (t == 0) out[0] = vv;
        }
        // ---- diagnostic: fixed 2,000,000-SM-cycle spin ----
        // f(MHz) = 2e6 / (dur_us - 66.0). Deterministic, no memory effects.
        if (t == 0) {
            long long c0 = clock64();
            while (clock64() - c0 < 2000000LL) { }
        }
    }
}

extern "C" void kernel_launch(void* const* d_in, const int* in_sizes, int n_in,
                              void* d_out, int out_size) {
    const float* ep    = (const float*)d_in[0];
    const float* nuc   = (const float*)d_in[1];
    const float* v     = (const float*)d_in[2];
    const float* b     = (const float*)d_in[3];
    const float* w     = (const float*)d_in[4];
    const float* c     = (const float*)d_in[5];
    const float* fw    = (const float*)d_in[6];
    const float* fb    = (const float*)d_in[7];
    const float* pi    = (const float*)d_in[8];
    const float* sigma = (const float*)d_in[9];
    const float* omega = (const float*)d_in[10];

    pre_kernel<<<1, 256>>>(ep, nuc);
    fused_kernel<<<GRID, 256>>>(ep, nuc, v, b, w, c, fw, fb, pi, sigma, omega,
                                (float*)d_out);
}

// round 15
// speedup vs baseline: 11.1258x; 11.1258x over previous
#include <cuda_runtime.h>
#include <math.h>
#include <stdint.h>

#define NEL 32
#define NUP 16
#define NI  32
#define NL  16
#define NK  16
#define H1  128
#define H2  4
#define FLEN 392
#define GRID 128

// ---- device-global state (no allocation allowed) ----
__device__ float g_sh[2][NEL][H1];
__device__ float g_rN[NEL][NI];
__device__ float g_phi[NK][2][16][16];
__device__ float g_det[NK][2];
__device__ unsigned g_main[2];          // [0] = layer epochs (monotonic, +32/epoch), [1] = det
__device__ unsigned g_cbar[32][32];     // per-cluster counters, one 128B line each ([n][0])

// ---------------- primitives ----------------
__device__ __forceinline__ unsigned ld_acq(const unsigned* p) {
    unsigned v;
    asm volatile("ld.acquire.gpu.global.u32 %0, [%1];" : "=r"(v) : "l"(p) : "memory");
    return v;
}
__device__ __forceinline__ void red_rel_add1(unsigned* p) {
    asm volatile("red.release.gpu.global.add.u32 [%0], 1;" :: "l"(p) : "memory");
}
__device__ __forceinline__ void cluster_arrive() {
    asm volatile("barrier.cluster.arrive.aligned;" ::: "memory");
}
__device__ __forceinline__ void cluster_wait() {
    asm volatile("barrier.cluster.wait.aligned;" ::: "memory");
}
__device__ __forceinline__ uint32_t mapa_addr(uint32_t saddr, int rank) {
    uint32_t r;
    asm("mapa.shared::cluster.u32 %0, %1, %2;" : "=r"(r) : "r"(saddr), "r"(rank));
    return r;
}
__device__ __forceinline__ void st_dsm(uint32_t saddr, float v) {
    asm volatile("st.shared::cluster.f32 [%0], %1;" :: "r"(saddr), "f"(v) : "memory");
}
__device__ __forceinline__ void st_dsm_rel_u32(uint32_t saddr, unsigned v) {
    asm volatile("st.release.cluster.shared::cluster.u32 [%0], %1;"
                 :: "r"(saddr), "r"(v) : "memory");
}
__device__ __forceinline__ unsigned ld_acq_sh(uint32_t saddr) {
    unsigned v;
    asm volatile("ld.acquire.cluster.shared::cta.u32 %0, [%1];"
                 : "=r"(v) : "r"(saddr) : "memory");
    return v;
}

// Hierarchical chip barrier.
// arrive: every block REDs its cluster line; leader aggregates into g_main[0].
__device__ __forceinline__ void chip_arrive(int n, int og, unsigned cl_target) {
    __syncthreads();
    if (threadIdx.x == 0) {
        red_rel_add1(&g_cbar[n][0]);
        if (og == 0) {
            while (ld_acq(&g_cbar[n][0]) < cl_target) { }
            red_rel_add1(&g_main[0]);
        }
    }
}
// wait for epoch e: leaders poll the main word (32 pollers), then flip peers'
// local smem epoch flags via DSMEM; peers spin on their own smem.
__device__ __forceinline__ void chip_wait(int og, unsigned e, uint32_t flag_s) {
    if (threadIdx.x == 0) {
        if (og == 0) {
            while (ld_acq(&g_main[0]) < 32u * e) { }
            for (int rk = 1; rk < 4; rk++)
                st_dsm_rel_u32(mapa_addr(flag_s, rk), e);
        } else {
            while (ld_acq_sh(flag_s) < e) { }
        }
    }
    __syncthreads();
}

// ---------------------------------------------------------------------------
// Preprocess: sh^0 + rN + zero counters (every replay)
// ---------------------------------------------------------------------------
__global__ void pre_kernel(const float* __restrict__ ep,
                           const float* __restrict__ nuc) {
    int t = threadIdx.x;
    if (t < 2) g_main[t] = 0;
    if (t < 32) g_cbar[t][0] = 0;
    for (int p = t; p < NEL * NI; p += blockDim.x) {
        int j = p >> 5, m = p & 31;
        float dx = ep[j * 3 + 0] - nuc[m * 3 + 0];
        float dy = ep[j * 3 + 1] - nuc[m * 3 + 1];
        float dz = ep[j * 3 + 2] - nuc[m * 3 + 2];
        float r  = sqrtf(dx * dx + dy * dy + dz * dz);
        g_sh[0][j][m * 3 + 0] = dx;
        g_sh[0][j][m * 3 + 1] = dy;
        g_sh[0][j][m * 3 + 2] = dz;
        g_sh[0][j][3 * NI + m] = r;
        g_rN[j][m] = r;
    }
}

// ---------------------------------------------------------------------------
// Fused persistent kernel — R11 compute, hierarchical barrier.
// ---------------------------------------------------------------------------
__global__ void __launch_bounds__(256, 1) __cluster_dims__(4, 1, 1) fused_kernel(
    const float* __restrict__ ep, const float* __restrict__ nuc,
    const float* __restrict__ v,
    const float* __restrict__ b,  const float* __restrict__ w,
    const float* __restrict__ c,  const float* __restrict__ fw,
    const float* __restrict__ fb, const float* __restrict__ pi,
    const float* __restrict__ sigma, const float* __restrict__ omega,
    float* __restrict__ out)
{
    __shared__ unsigned epoch_flag;
    __shared__ float m_s[256];
    __shared__ float sh_loc[2][H1];
    __shared__ float pd[2][4][4];
    __shared__ float dg_s[8];
    __shared__ float part_s[8][33];
    __shared__ float A[16][17];
    __shared__ float fac[16];
    __shared__ int   pivs;
    __shared__ float dsh;

    const int t    = threadIdx.x;
    const int n    = blockIdx.x >> 2;
    const int og   = blockIdx.x & 3;
    const int c4   = t & 7;
    const int fs   = t >> 3;
    const int lane = t & 31, wrp = t >> 5;
    const int dj   = og * 8 + t;

    const uint32_t shloc_s = (uint32_t)__cvta_generic_to_shared(&sh_loc[0][0]);
    const uint32_t pd_s    = (uint32_t)__cvta_generic_to_shared(&pd[0][0][0]);
    const uint32_t flag_s  = (uint32_t)__cvta_generic_to_shared(&epoch_flag);

    if (t == 0) epoch_flag = 0;

    // ---------------- prologue: local sh^0, dh^0 + partials ----------------
    if (t < H1) {
        float val;
        if (t < 96) {
            int m = t / 3, cp = t % 3;
            val = ep[n * 3 + cp] - nuc[m * 3 + cp];
        } else {
            int m = t - 96;
            float dx = ep[n * 3 + 0] - nuc[m * 3 + 0];
            float dy = ep[n * 3 + 1] - nuc[m * 3 + 1];
            float dz = ep[n * 3 + 2] - nuc[m * 3 + 2];
            val = sqrtf(dx * dx + dy * dy + dz * dz);
        }
        sh_loc[0][t] = val;
    }
    float4 d4;
    if (t < 8) {
        float dx = ep[n * 3 + 0] - ep[dj * 3 + 0];
        float dy = ep[n * 3 + 1] - ep[dj * 3 + 1];
        float dz = ep[n * 3 + 2] - ep[dj * 3 + 2];
        d4 = make_float4(dx, dy, dz, sqrtf(dx * dx + dy * dy + dz * dz));
        float4 s = d4;
        s.x += __shfl_down_sync(0xffu, s.x, 4, 8);
        s.y += __shfl_down_sync(0xffu, s.y, 4, 8);
        s.z += __shfl_down_sync(0xffu, s.z, 4, 8);
        s.w += __shfl_down_sync(0xffu, s.w, 4, 8);
        s.x += __shfl_down_sync(0xffu, s.x, 2, 8);
        s.y += __shfl_down_sync(0xffu, s.y, 2, 8);
        s.z += __shfl_down_sync(0xffu, s.z, 2, 8);
        s.w += __shfl_down_sync(0xffu, s.w, 2, 8);
        s.x += __shfl_down_sync(0xffu, s.x, 1, 8);
        s.y += __shfl_down_sync(0xffu, s.y, 1, 8);
        s.z += __shfl_down_sync(0xffu, s.z, 1, 8);
        s.w += __shfl_down_sync(0xffu, s.w, 1, 8);
        if (t == 0) {
            uint32_t base = pd_s + (0 * 4 + og) * 16;
            for (int rk = 0; rk < 4; rk++) {
                uint32_t ra = mapa_addr(base, rk);
                st_dsm(ra + 0,  s.x);
                st_dsm(ra + 4,  s.y);
                st_dsm(ra + 8,  s.z);
                st_dsm(ra + 12, s.w);
            }
        }
    }
    cluster_arrive();

    float4 wr[13];
    float4 dw0, dw1, dw2, dw3, dc4;

#pragma unroll 1
    for (int l = 0; l < NL; l++) {
        const int p   = l & 1;
        const int cur = l & 1, nxt = cur ^ 1;

        {
            const float* vp = v + (((size_t)l * NEL + n) * FLEN) * H1 + og * 32 + c4 * 4;
#pragma unroll
            for (int i = 0; i < 12; i++)
                wr[i] = *reinterpret_cast<const float4*>(vp + (size_t)(fs + 32 * i) * H1);
            if (fs < 8)
                wr[12] = *reinterpret_cast<const float4*>(vp + (size_t)(fs + 384) * H1);
        }
        float bias_r = 0.f;
        if (t < 32) bias_r = b[((size_t)l * NEL + n) * H1 + og * 32 + t];
        const bool do_d = (t < 8) && (l < NL - 1);
        if (do_d) {
            const float* wp = w + ((size_t)(l * NEL + n) * NEL + dj) * 16;
            dw0 = *reinterpret_cast<const float4*>(wp);
            dw1 = *reinterpret_cast<const float4*>(wp + 4);
            dw2 = *reinterpret_cast<const float4*>(wp + 8);
            dw3 = *reinterpret_cast<const float4*>(wp + 12);
            dc4 = *reinterpret_cast<const float4*>(
                c + ((size_t)(l * NEL + n) * NEL + dj) * 4);
        }

        cluster_wait();
        if (t < 8) {
            int d = t & 3;
            float a = (t < 4) ? (pd[p][0][d] + pd[p][1][d])
                              : (pd[p][2][d] + pd[p][3][d]);
            dg_s[t] = a * (1.0f / 16);
        }
        __syncthreads();

        float4 acc = make_float4(0.f, 0.f, 0.f, 0.f);
#pragma unroll
        for (int i = 0; i < 4; i++) {
            float s = sh_loc[p][fs + 32 * i];
            acc.x += s * wr[i].x; acc.y += s * wr[i].y;
            acc.z += s * wr[i].z; acc.w += s * wr[i].w;
        }
        if (fs < 8) {
            float s = dg_s[fs];
            acc.x += s * wr[12].x; acc.y += s * wr[12].y;
            acc.z += s * wr[12].z; acc.w += s * wr[12].w;
        }

        float4 od;
        if (do_d) {
            float o0 = d4.x * dw0.x + d4.y * dw1.x + d4.z * dw2.x + d4.w * dw3.x;
            float o1 = d4.x * dw0.y + d4.y * dw1.y + d4.z * dw2.y + d4.w * dw3.y;
            float o2 = d4.x * dw0.z + d4.y * dw1.z + d4.z * dw2.z + d4.w * dw3.z;
            float o3 = d4.x * dw0.w + d4.y * dw1.w + d4.z * dw2.w + d4.w * dw3.w;
            od.x = tanhf(o0 + dc4.x) + d4.x;
            od.y = tanhf(o1 + dc4.y) + d4.y;
            od.z = tanhf(o2 + dc4.z) + d4.z;
            od.w = tanhf(o3 + dc4.w) + d4.w;
        }

        if (l > 0) chip_wait(og, (unsigned)l, flag_s);

        if (t < 128) {
            float s = 0.f;
#pragma unroll
            for (int r = 0; r < NUP; r++) s += __ldcg(&g_sh[cur][r][t]);
            m_s[t] = s * (1.0f / 16);
        } else {
            int o = t - 128;
            float s = 0.f;
#pragma unroll
            for (int r = NUP; r < NEL; r++) s += __ldcg(&g_sh[cur][r][o]);
            m_s[128 + o] = s * (1.0f / 16);
        }
        __syncthreads();

#pragma unroll
        for (int q = 0; q < 8; q++) {
            float s = m_s[fs + 32 * q];
            acc.x += s * wr[4 + q].x; acc.y += s * wr[4 + q].y;
            acc.z += s * wr[4 + q].z; acc.w += s * wr[4 + q].w;
        }

#pragma unroll
        for (int off = 16; off >= 8; off >>= 1) {
            acc.x += __shfl_down_sync(0xffffffffu, acc.x, off);
            acc.y += __shfl_down_sync(0xffffffffu, acc.y, off);
            acc.z += __shfl_down_sync(0xffffffffu, acc.z, off);
            acc.w += __shfl_down_sync(0xffffffffu, acc.w, off);
        }
        if (lane < 8) {
            part_s[wrp][lane * 4 + 0] = acc.x;
            part_s[wrp][lane * 4 + 1] = acc.y;
            part_s[wrp][lane * 4 + 2] = acc.z;
            part_s[wrp][lane * 4 + 3] = acc.w;
        }
        __syncthreads();

        if (t < 32) {
            float a = part_s[0][t];
#pragma unroll
            for (int ww = 1; ww < 8; ww++) a += part_s[ww][t];
            int o = og * 32 + t;
            float val = tanhf(a + bias_r) + sh_loc[p][o];
            __stcg(&g_sh[nxt][n][o], val);
            if (l < NL - 1) {
                uint32_t base = shloc_s + ((p ^ 1) * H1 + o) * 4;
#pragma unroll
                for (int rk = 0; rk < 4; rk++)
                    st_dsm(mapa_addr(base, rk), val);
            }
        }

        if (do_d) {
            d4 = od;
            float4 s = d4;
            s.x += __shfl_down_sync(0xffu, s.x, 4, 8);
            s.y += __shfl_down_sync(0xffu, s.y, 4, 8);
            s.z += __shfl_down_sync(0xffu, s.z, 4, 8);
            s.w += __shfl_down_sync(0xffu, s.w, 4, 8);
            s.x += __shfl_down_sync(0xffu, s.x, 2, 8);
            s.y += __shfl_down_sync(0xffu, s.y, 2, 8);
            s.z += __shfl_down_sync(0xffu, s.z, 2, 8);
            s.w += __shfl_down_sync(0xffu, s.w, 2, 8);
            s.x += __shfl_down_sync(0xffu, s.x, 1, 8);
            s.y += __shfl_down_sync(0xffu, s.y, 1, 8);
            s.z += __shfl_down_sync(0xffu, s.z, 1, 8);
            s.w += __shfl_down_sync(0xffu, s.w, 1, 8);
            if (t == 0) {
                uint32_t base = pd_s + (((p ^ 1) * 4 + og) * 4) * 4;
                for (int rk = 0; rk < 4; rk++) {
                    uint32_t ra = mapa_addr(base, rk);
                    st_dsm(ra + 0,  s.x);
                    st_dsm(ra + 4,  s.y);
                    st_dsm(ra + 8,  s.z);
                    st_dsm(ra + 12, s.w);
                }
            }
        }
        if (l < NL - 1) cluster_arrive();
        chip_arrive(n, og, 4u * (unsigned)(l + 1));
    }

    // ================= phi =================
    chip_wait(og, (unsigned)NL, flag_s);
    {
        const int k    = blockIdx.x >> 3;
        const int i    = (blockIdx.x & 7) * 4 + (t >> 6);
        const int spin = i >> 4;
        const int tl   = t & 63;
        const int jl   = tl >> 2, s = tl & 3;
        const int j    = spin * 16 + jl;
        const float* fwp = fw + (size_t)(k * NEL + i) * H1;
        float dot = 0.f;
#pragma unroll
        for (int q = 0; q < 32; q++)
            dot += fwp[s + 4 * q] * __ldcg(&g_sh[0][j][s + 4 * q]);
        const float* pip = pi    + (size_t)(k * NEL + i) * NI;
        const float* sgp = sigma + (size_t)(k * NEL + i) * NI;
        float env = 0.f;
#pragma unroll
        for (int q = 0; q < 8; q++) {
            int m = s * 8 + q;
            env += pip[m] * __expf(-fabsf(sgp[m]) * g_rN[j][m]);
        }
        dot += __shfl_down_sync(0xffffffffu, dot, 2, 4);
        dot += __shfl_down_sync(0xffffffffu, dot, 1, 4);
        env += __shfl_down_sync(0xffffffffu, env, 2, 4);
        env += __shfl_down_sync(0xffffffffu, env, 1, 4);
        if (s == 0)
            __stcg(&g_phi[k][spin][i & 15][jl], (dot + fb[k * NEL + i]) * env);
    }
    chip_arrive(n, og, 4u * (unsigned)(NL + 1));

    // ================= determinants (blocks 0..31) =================
    chip_wait(og, (unsigned)(NL + 1), flag_s);
    if (blockIdx.x < 32) {
        const int k = blockIdx.x >> 1, spin = blockIdx.x & 1;
        const int r = t >> 4, cc = t & 15;
        A[r][cc] = __ldcg(&g_phi[k][spin][r][cc]);
        if (t == 0) dsh = 1.0f;
        __syncthreads();
        for (int pp = 0; pp < 16; pp++) {
            if (t == 0) {
                int best = pp;
                float bv = fabsf(A[pp][pp]);
                for (int rr = pp + 1; rr < 16; rr++) {
                    float v2 = fabsf(A[rr][pp]);
                    if (v2 > bv) { bv = v2; best = rr; }
                }
                pivs = best;
                if (best != pp) dsh = -dsh;
            }
            __syncthreads();
            int piv = pivs;
            if (piv != pp && t < 16) {
                float tmp = A[pp][t]; A[pp][t] = A[piv][t]; A[piv][t] = tmp;
            }
            __syncthreads();
            if (t < 16 && t > pp) fac[t] = A[t][pp] / A[pp][pp];
            if (t == 0) dsh *= A[pp][pp];
            __syncthreads();
            if (r > pp && cc > pp) A[r][cc] -= fac[r] * A[pp][cc];
            __syncthreads();
        }
        if (t == 0) __stcg(&g_det[k][spin], dsh);
        __syncthreads();
        if (t == 0) red_rel_add1(&g_main[1]);
    }

    // ================= final reduction (block 0) =================
    if (blockIdx.x == 0) {
        if (t == 0) { while (ld_acq(&g_main[1]) < 32u) { } }
        __syncthreads();
        if (t < 32) {
            float vv = (t < NK) ? omega[t] * __ldcg(&g_det[t][0]) * __ldcg(&g_det[t][1])
                                : 0.0f;
#pragma unroll
            for (int off = 16; off; off >>= 1)
                vv += __shfl_down_sync(0xffffffffu, vv, off);
            if (t == 0) out[0] = vv;
        }
    }
}

extern "C" void kernel_launch(void* const* d_in, const int* in_sizes, int n_in,
                              void* d_out, int out_size) {
    const float* ep    = (const float*)d_in[0];
    const float* nuc   = (const float*)d_in[1];
    const float* v     = (const float*)d_in[2];
    const float* b     = (const float*)d_in[3];
    const float* w     = (const float*)d_in[4];
    const float* c     = (const float*)d_in[5];
    const float* fw    = (const float*)d_in[6];
    const float* fb    = (const float*)d_in[7];
    const float* pi    = (const float*)d_in[8];
    const float* sigma = (const float*)d_in[9];
    const float* omega = (const float*)d_in[10];

    pre_kernel<<<1, 256>>>(ep, nuc);
    fused_kernel<<<GRID, 256>>>(ep, nuc, v, b, w, c, fw, fb, pi, sigma, omega,
                                (float*)d_out);
}

// round 16
// speedup vs baseline: 16.1543x; 1.4520x over previous
#include <cuda.h>
#include <cuda_runtime.h>
#include <math.h>
#include <stdint.h>

#define NEL 32
#define NUP 16
#define NI  32
#define NL  16
#define NK  16
#define H1  128
#define H2  4
#define FLEN 392
#define GRID 128

#define STAGE_BYTES (FLEN * 128)        // 50176 B: [392 rows][32 floats]
#define DYN_BYTES   (2 * STAGE_BYTES)   // double buffer

// ---- device-global state (no allocation allowed) ----
__device__ float g_sh[2][NEL][H1];
__device__ float g_rN[NEL][NI];
__device__ float g_phi[NK][2][16][16];
__device__ float g_det[NK][2];
__device__ unsigned g_bar[NL + 2];

// ---------------- R2's barrier, verbatim ----------------
__device__ __forceinline__ unsigned ld_acq(const unsigned* p) {
    unsigned v;
    asm volatile("ld.acquire.gpu.global.u32 %0, [%1];" : "=r"(v) : "l"(p) : "memory");
    return v;
}
__device__ __forceinline__ void red_rel_add1(unsigned* p) {
    asm volatile("red.release.gpu.global.add.u32 [%0], 1;" :: "l"(p) : "memory");
}
__device__ __forceinline__ void bar_arrive(int idx) {
    __syncthreads();
    if (threadIdx.x == 0) red_rel_add1(&g_bar[idx]);
}
__device__ __forceinline__ void bar_wait(int idx, unsigned target) {
    if (threadIdx.x == 0) {
        while (ld_acq(&g_bar[idx]) < target) { }
    }
    __syncthreads();
}

// ---------------- cluster / DSMEM helpers ----------------
__device__ __forceinline__ void cluster_arrive() {
    asm volatile("barrier.cluster.arrive.aligned;" ::: "memory");
}
__device__ __forceinline__ void cluster_wait() {
    asm volatile("barrier.cluster.wait.aligned;" ::: "memory");
}
__device__ __forceinline__ uint32_t mapa_addr(uint32_t saddr, int rank) {
    uint32_t r;
    asm("mapa.shared::cluster.u32 %0, %1, %2;" : "=r"(r) : "r"(saddr), "r"(rank));
    return r;
}
__device__ __forceinline__ void st_dsm(uint32_t saddr, float v) {
    asm volatile("st.shared::cluster.f32 [%0], %1;" :: "r"(saddr), "f"(v) : "memory");
}

// ---------------- TMA / mbarrier helpers ----------------
__device__ __forceinline__ void mbar_init(uint32_t mbar, unsigned cnt) {
    asm volatile("mbarrier.init.shared.b64 [%0], %1;" :: "r"(mbar), "r"(cnt) : "memory");
}
__device__ __forceinline__ void mbar_expect_tx(uint32_t mbar, unsigned bytes) {
    asm volatile("mbarrier.arrive.expect_tx.shared.b64 _, [%0], %1;"
                 :: "r"(mbar), "r"(bytes) : "memory");
}
__device__ __forceinline__ void mbar_wait(uint32_t mbar, unsigned parity) {
    asm volatile(
        "{\n\t"
        ".reg .pred P;\n\t"
        "WL_%=:\n\t"
        "mbarrier.try_wait.parity.acquire.cta.shared::cta.b64 P, [%0], %1, 0x989680;\n\t"
        "@P bra WD_%=;\n\t"
        "bra WL_%=;\n\t"
        "WD_%=:\n\t"
        "}"
        :: "r"(mbar), "r"(parity) : "memory");
}
__device__ __forceinline__ void tma_load_3d(uint32_t dst, const CUtensorMap* tm,
                                            int c0, int c1, int c2, uint32_t mbar) {
    asm volatile(
        "cp.async.bulk.tensor.3d.shared::cta.global.tile.mbarrier::complete_tx::bytes "
        "[%0], [%1, {%2, %3, %4}], [%5];"
        :: "r"(dst), "l"(tm), "r"(c0), "r"(c1), "r"(c2), "r"(mbar) : "memory");
}

// ---------------------------------------------------------------------------
// Preprocess: sh^0 + rN + zero counters (every replay)
// ---------------------------------------------------------------------------
__global__ void pre_kernel(const float* __restrict__ ep,
                           const float* __restrict__ nuc) {
    int t = threadIdx.x;
    if (t < NL + 2) g_bar[t] = 0;
    for (int p = t; p < NEL * NI; p += blockDim.x) {
        int j = p >> 5, m = p & 31;
        float dx = ep[j * 3 + 0] - nuc[m * 3 + 0];
        float dy = ep[j * 3 + 1] - nuc[m * 3 + 1];
        float dz = ep[j * 3 + 2] - nuc[m * 3 + 2];
        float r  = sqrtf(dx * dx + dy * dy + dz * dz);
        g_sh[0][j][m * 3 + 0] = dx;
        g_sh[0][j][m * 3 + 1] = dy;
        g_sh[0][j][m * 3 + 2] = dz;
        g_sh[0][j][3 * NI + m] = r;
        g_rN[j][m] = r;
    }
}

// ---------------------------------------------------------------------------
// Fused persistent kernel — R11 compute; weights streamed via TMA double-buffer.
// ---------------------------------------------------------------------------
__global__ void __launch_bounds__(256, 1) __cluster_dims__(4, 1, 1) fused_kernel(
    const __grid_constant__ CUtensorMap tmap,
    const float* __restrict__ ep, const float* __restrict__ nuc,
    const float* __restrict__ b,  const float* __restrict__ w,
    const float* __restrict__ c,  const float* __restrict__ fw,
    const float* __restrict__ fb, const float* __restrict__ pi,
    const float* __restrict__ sigma, const float* __restrict__ omega,
    float* __restrict__ out)
{
    extern __shared__ __align__(128) char dyn[];
    __shared__ __align__(8) unsigned long long mbar_st[2];
    __shared__ float m_s[256];
    __shared__ float sh_loc[2][H1];
    __shared__ float pd[2][4][4];
    __shared__ float dg_s[8];
    __shared__ float part_s[8][33];
    __shared__ float A[16][17];
    __shared__ float fac[16];
    __shared__ int   pivs;
    __shared__ float dsh;

    const int t    = threadIdx.x;
    const int n    = blockIdx.x >> 2;
    const int og   = blockIdx.x & 3;
    const int c4   = t & 7;
    const int fs   = t >> 3;
    const int lane = t & 31, wrp = t >> 5;
    const int dj   = og * 8 + t;

    const uint32_t shloc_s = (uint32_t)__cvta_generic_to_shared(&sh_loc[0][0]);
    const uint32_t pd_s    = (uint32_t)__cvta_generic_to_shared(&pd[0][0][0]);
    const uint32_t dyn_s   = (uint32_t)__cvta_generic_to_shared(dyn);
    const uint32_t mbar0   = (uint32_t)__cvta_generic_to_shared(&mbar_st[0]);
    const uint32_t mbar1   = (uint32_t)__cvta_generic_to_shared(&mbar_st[1]);

    // ---- mbarrier init + first two TMA stages ----
    if (t == 0) {
        mbar_init(mbar0, 1);
        mbar_init(mbar1, 1);
    }
    __syncthreads();
    if (t == 0) {
        // layer 0 -> stage 0
        mbar_expect_tx(mbar0, STAGE_BYTES);
        tma_load_3d(dyn_s, &tmap, og * 32, 0,   0 * NEL + n, mbar0);
        tma_load_3d(dyn_s + 196 * 128, &tmap, og * 32, 196, 0 * NEL + n, mbar0);
        // layer 1 -> stage 1
        mbar_expect_tx(mbar1, STAGE_BYTES);
        tma_load_3d(dyn_s + STAGE_BYTES, &tmap, og * 32, 0,   1 * NEL + n, mbar1);
        tma_load_3d(dyn_s + STAGE_BYTES + 196 * 128, &tmap, og * 32, 196,
                    1 * NEL + n, mbar1);
    }

    // ---------------- prologue: local sh^0, dh^0 + partials ----------------
    if (t < H1) {
        float val;
        if (t < 96) {
            int m = t / 3, cp = t % 3;
            val = ep[n * 3 + cp] - nuc[m * 3 + cp];
        } else {
            int m = t - 96;
            float dx = ep[n * 3 + 0] - nuc[m * 3 + 0];
            float dy = ep[n * 3 + 1] - nuc[m * 3 + 1];
            float dz = ep[n * 3 + 2] - nuc[m * 3 + 2];
            val = sqrtf(dx * dx + dy * dy + dz * dz);
        }
        sh_loc[0][t] = val;
    }
    float4 d4;
    if (t < 8) {
        float dx = ep[n * 3 + 0] - ep[dj * 3 + 0];
        float dy = ep[n * 3 + 1] - ep[dj * 3 + 1];
        float dz = ep[n * 3 + 2] - ep[dj * 3 + 2];
        d4 = make_float4(dx, dy, dz, sqrtf(dx * dx + dy * dy + dz * dz));
        float4 s = d4;
        s.x += __shfl_down_sync(0xffu, s.x, 4, 8);
        s.y += __shfl_down_sync(0xffu, s.y, 4, 8);
        s.z += __shfl_down_sync(0xffu, s.z, 4, 8);
        s.w += __shfl_down_sync(0xffu, s.w, 4, 8);
        s.x += __shfl_down_sync(0xffu, s.x, 2, 8);
        s.y += __shfl_down_sync(0xffu, s.y, 2, 8);
        s.z += __shfl_down_sync(0xffu, s.z, 2, 8);
        s.w += __shfl_down_sync(0xffu, s.w, 2, 8);
        s.x += __shfl_down_sync(0xffu, s.x, 1, 8);
        s.y += __shfl_down_sync(0xffu, s.y, 1, 8);
        s.z += __shfl_down_sync(0xffu, s.z, 1, 8);
        s.w += __shfl_down_sync(0xffu, s.w, 1, 8);
        if (t == 0) {
            uint32_t base = pd_s + (0 * 4 + og) * 16;
            for (int rk = 0; rk < 4; rk++) {
                uint32_t ra = mapa_addr(base, rk);
                st_dsm(ra + 0,  s.x);
                st_dsm(ra + 4,  s.y);
                st_dsm(ra + 8,  s.z);
                st_dsm(ra + 12, s.w);
            }
        }
    }
    cluster_arrive();

    float4 dw0, dw1, dw2, dw3, dc4;

#pragma unroll 1
    for (int l = 0; l < NL; l++) {
        const int p   = l & 1;
        const int cur = l & 1, nxt = cur ^ 1;
        const uint32_t stage = (l & 1) ? mbar1 : mbar0;
        const float4* wst = (const float4*)(dyn + (l & 1) * STAGE_BYTES);

        float bias_r = 0.f;
        if (t < 32) bias_r = b[((size_t)l * NEL + n) * H1 + og * 32 + t];
        const bool do_d = (t < 8) && (l < NL - 1);
        if (do_d) {
            const float* wp = w + ((size_t)(l * NEL + n) * NEL + dj) * 16;
            dw0 = *reinterpret_cast<const float4*>(wp);
            dw1 = *reinterpret_cast<const float4*>(wp + 4);
            dw2 = *reinterpret_cast<const float4*>(wp + 8);
            dw3 = *reinterpret_cast<const float4*>(wp + 12);
            dc4 = *reinterpret_cast<const float4*>(
                c + ((size_t)(l * NEL + n) * NEL + dj) * 4);
        }

        // ---- wait weights for this layer (TMA complete) ----
        mbar_wait(stage, (unsigned)((l >> 1) & 1));

        cluster_wait();
        if (t < 8) {
            int d = t & 3;
            float a = (t < 4) ? (pd[p][0][d] + pd[p][1][d])
                              : (pd[p][2][d] + pd[p][3][d]);
            dg_s[t] = a * (1.0f / 16);
        }
        __syncthreads();

        // ---- LOCAL matvec (rows 0..127 own sh, 384..391 dg) ----
        float4 acc = make_float4(0.f, 0.f, 0.f, 0.f);
#pragma unroll
        for (int i = 0; i < 4; i++) {
            int r = fs + 32 * i;
            float s = sh_loc[p][r];
            float4 wv = wst[r * 8 + c4];
            acc.x += s * wv.x; acc.y += s * wv.y;
            acc.z += s * wv.z; acc.w += s * wv.w;
        }
        if (fs < 8) {
            int r = fs + 384;
            float s = dg_s[fs];
            float4 wv = wst[r * 8 + c4];
            acc.x += s * wv.x; acc.y += s * wv.y;
            acc.z += s * wv.z; acc.w += s * wv.w;
        }

        // ---- dh update (register-resident) ----
        float4 od;
        if (do_d) {
            float o0 = d4.x * dw0.x + d4.y * dw1.x + d4.z * dw2.x + d4.w * dw3.x;
            float o1 = d4.x * dw0.y + d4.y * dw1.y + d4.z * dw2.y + d4.w * dw3.y;
            float o2 = d4.x * dw0.z + d4.y * dw1.z + d4.z * dw2.z + d4.w * dw3.z;
            float o3 = d4.x * dw0.w + d4.y * dw1.w + d4.z * dw2.w + d4.w * dw3.w;
            od.x = tanhf(o0 + dc4.x) + d4.x;
            od.y = tanhf(o1 + dc4.y) + d4.y;
            od.z = tanhf(o2 + dc4.z) + d4.z;
            od.w = tanhf(o3 + dc4.w) + d4.w;
        }

        // ---- chip barrier ----
        if (l > 0) bar_wait(l - 1, GRID);

        // ---- mean gather ----
        if (t < 128) {
            float s = 0.f;
#pragma unroll
            for (int r = 0; r < NUP; r++) s += __ldcg(&g_sh[cur][r][t]);
            m_s[t] = s * (1.0f / 16);
        } else {
            int o = t - 128;
            float s = 0.f;
#pragma unroll
            for (int r = NUP; r < NEL; r++) s += __ldcg(&g_sh[cur][r][o]);
            m_s[128 + o] = s * (1.0f / 16);
        }
        __syncthreads();

        // ---- MEAN matvec (rows 128..383) ----
#pragma unroll
        for (int q = 0; q < 8; q++) {
            int r = fs + 128 + 32 * q;
            float s = m_s[fs + 32 * q];
            float4 wv = wst[r * 8 + c4];
            acc.x += s * wv.x; acc.y += s * wv.y;
            acc.z += s * wv.z; acc.w += s * wv.w;
        }

        // ---- reduce ----
#pragma unroll
        for (int off = 16; off >= 8; off >>= 1) {
            acc.x += __shfl_down_sync(0xffffffffu, acc.x, off);
            acc.y += __shfl_down_sync(0xffffffffu, acc.y, off);
            acc.z += __shfl_down_sync(0xffffffffu, acc.z, off);
            acc.w += __shfl_down_sync(0xffffffffu, acc.w, off);
        }
        if (lane < 8) {
            part_s[wrp][lane * 4 + 0] = acc.x;
            part_s[wrp][lane * 4 + 1] = acc.y;
            part_s[wrp][lane * 4 + 2] = acc.z;
            part_s[wrp][lane * 4 + 3] = acc.w;
        }
        __syncthreads();

        // ---- tail ----
        if (t < 32) {
            float a = part_s[0][t];
#pragma unroll
            for (int ww = 1; ww < 8; ww++) a += part_s[ww][t];
            int o = og * 32 + t;
            float val = tanhf(a + bias_r) + sh_loc[p][o];
            __stcg(&g_sh[nxt][n][o], val);
            if (l < NL - 1) {
                uint32_t base = shloc_s + ((p ^ 1) * H1 + o) * 4;
#pragma unroll
                for (int rk = 0; rk < 4; rk++)
                    st_dsm(mapa_addr(base, rk), val);
            }
        }

        if (do_d) {
            d4 = od;
            float4 s = d4;
            s.x += __shfl_down_sync(0xffu, s.x, 4, 8);
            s.y += __shfl_down_sync(0xffu, s.y, 4, 8);
            s.z += __shfl_down_sync(0xffu, s.z, 4, 8);
            s.w += __shfl_down_sync(0xffu, s.w, 4, 8);
            s.x += __shfl_down_sync(0xffu, s.x, 2, 8);
            s.y += __shfl_down_sync(0xffu, s.y, 2, 8);
            s.z += __shfl_down_sync(0xffu, s.z, 2, 8);
            s.w += __shfl_down_sync(0xffu, s.w, 2, 8);
            s.x += __shfl_down_sync(0xffu, s.x, 1, 8);
            s.y += __shfl_down_sync(0xffu, s.y, 1, 8);
            s.z += __shfl_down_sync(0xffu, s.z, 1, 8);
            s.w += __shfl_down_sync(0xffu, s.w, 1, 8);
            if (t == 0) {
                uint32_t base = pd_s + (((p ^ 1) * 4 + og) * 4) * 4;
                for (int rk = 0; rk < 4; rk++) {
                    uint32_t ra = mapa_addr(base, rk);
                    st_dsm(ra + 0,  s.x);
                    st_dsm(ra + 4,  s.y);
                    st_dsm(ra + 8,  s.z);
                    st_dsm(ra + 12, s.w);
                }
            }
        }
        if (l < NL - 1) cluster_arrive();
        bar_arrive(l);   // __syncthreads inside: all reads of this stage done

        // ---- refill this stage with layer l+2 ----
        if (l + 2 < NL && t == 0) {
            uint32_t sdst = dyn_s + (l & 1) * STAGE_BYTES;
            mbar_expect_tx(stage, STAGE_BYTES);
            tma_load_3d(sdst, &tmap, og * 32, 0,   (l + 2) * NEL + n, stage);
            tma_load_3d(sdst + 196 * 128, &tmap, og * 32, 196, (l + 2) * NEL + n, stage);
        }
    }

    // ================= phi (diagonal 16x16 blocks only) =================
    bar_wait(NL - 1, GRID);
    {
        const int k    = blockIdx.x >> 3;
        const int i    = (blockIdx.x & 7) * 4 + (t >> 6);
        const int spin = i >> 4;
        const int tl   = t & 63;
        const int jl   = tl >> 2, s = tl & 3;
        const int j    = spin * 16 + jl;
        const float* fwp = fw + (size_t)(k * NEL + i) * H1;
        float dot = 0.f;
#pragma unroll
        for (int q = 0; q < 32; q++)
            dot += fwp[s + 4 * q] * __ldcg(&g_sh[0][j][s + 4 * q]);
        const float* pip = pi    + (size_t)(k * NEL + i) * NI;
        const float* sgp = sigma + (size_t)(k * NEL + i) * NI;
        float env = 0.f;
#pragma unroll
        for (int q = 0; q < 8; q++) {
            int m = s * 8 + q;
            env += pip[m] * __expf(-fabsf(sgp[m]) * g_rN[j][m]);
        }
        dot += __shfl_down_sync(0xffffffffu, dot, 2, 4);
        dot += __shfl_down_sync(0xffffffffu, dot, 1, 4);
        env += __shfl_down_sync(0xffffffffu, env, 2, 4);
        env += __shfl_down_sync(0xffffffffu, env, 1, 4);
        if (s == 0)
            __stcg(&g_phi[k][spin][i & 15][jl], (dot + fb[k * NEL + i]) * env);
    }
    bar_arrive(NL);

    // ================= determinants (blocks 0..31) =================
    if (blockIdx.x < 32) {
        bar_wait(NL, GRID);
        const int k = blockIdx.x >> 1, spin = blockIdx.x & 1;
        const int r = t >> 4, cc = t & 15;
        A[r][cc] = __ldcg(&g_phi[k][spin][r][cc]);
        if (t == 0) dsh = 1.0f;
        __syncthreads();
        for (int pp = 0; pp < 16; pp++) {
            if (t == 0) {
                int best = pp;
                float bv = fabsf(A[pp][pp]);
                for (int rr = pp + 1; rr < 16; rr++) {
                    float v2 = fabsf(A[rr][pp]);
                    if (v2 > bv) { bv = v2; best = rr; }
                }
                pivs = best;
                if (best != pp) dsh = -dsh;
            }
            __syncthreads();
            int piv = pivs;
            if (piv != pp && t < 16) {
                float tmp = A[pp][t]; A[pp][t] = A[piv][t]; A[piv][t] = tmp;
            }
            __syncthreads();
            if (t < 16 && t > pp) fac[t] = A[t][pp] / A[pp][pp];
            if (t == 0) dsh *= A[pp][pp];
            __syncthreads();
            if (r > pp && cc > pp) A[r][cc] -= fac[r] * A[pp][cc];
            __syncthreads();
        }
        if (t == 0) __stcg(&g_det[k][spin], dsh);
        bar_arrive(NL + 1);
    }

    // ================= final reduction (block 0) =================
    if (blockIdx.x == 0) {
        bar_wait(NL + 1, 32);
        if (t < 32) {
            float vv = (t < NK) ? omega[t] * __ldcg(&g_det[t][0]) * __ldcg(&g_det[t][1])
                                : 0.0f;
#pragma unroll
            for (int off = 16; off; off >>= 1)
                vv += __shfl_down_sync(0xffffffffu, vv, off);
            if (t == 0) out[0] = vv;
        }
    }
}

// ---------------------------------------------------------------------------
// Host side
// ---------------------------------------------------------------------------
typedef CUresult (*PFN_tme)(CUtensorMap*, CUtensorMapDataType, cuuint32_t, void*,
                            const cuuint64_t*, const cuuint64_t*, const cuuint32_t*,
                            const cuuint32_t*, CUtensorMapInterleave, CUtensorMapSwizzle,
                            CUtensorMapL2promotion, CUtensorMapFloatOOBfill);

extern "C" void kernel_launch(void* const* d_in, const int* in_sizes, int n_in,
                              void* d_out, int out_size) {
    const float* ep    = (const float*)d_in[0];
    const float* nuc   = (const float*)d_in[1];
    const float* v     = (const float*)d_in[2];
    const float* b     = (const float*)d_in[3];
    const float* w     = (const float*)d_in[4];
    const float* c     = (const float*)d_in[5];
    const float* fw    = (const float*)d_in[6];
    const float* fb    = (const float*)d_in[7];
    const float* pi    = (const float*)d_in[8];
    const float* sigma = (const float*)d_in[9];
    const float* omega = (const float*)d_in[10];

    // Build the TMA descriptor for v: [L*N][FLEN][H1] fp32.
    // dim0 = 128 elems (contiguous), dim1 = 392 rows (512B stride),
    // dim2 = 512 planes (200704B stride). Box = (32, 196, 1).
    CUtensorMap tmap;
    {
        static PFN_tme pfn = nullptr;       // resolved once per process (pure lookup)
        if (!pfn) {
            cudaDriverEntryPointQueryResult qres;
            void* fp = nullptr;
            cudaGetDriverEntryPoint("cuTensorMapEncodeTiled", &fp,
                                    cudaEnableDefault, &qres);
            pfn = (PFN_tme)fp;
        }
        cuuint64_t dims[3]    = {128, FLEN, (cuuint64_t)NL * NEL};
        cuuint64_t strides[2] = {512, (cuuint64_t)FLEN * 512};
        cuuint32_t box[3]     = {32, 196, 1};
        cuuint32_t estr[3]    = {1, 1, 1};
        pfn(&tmap, CU_TENSOR_MAP_DATA_TYPE_FLOAT32, 3, (void*)v,
            dims, strides, box, estr,
            CU_TENSOR_MAP_INTERLEAVE_NONE, CU_TENSOR_MAP_SWIZZLE_NONE,
            CU_TENSOR_MAP_L2_PROMOTION_L2_128B, CU_TENSOR_MAP_FLOAT_OOB_FILL_NONE);
    }

    cudaFuncSetAttribute(fused_kernel,
                         cudaFuncAttributeMaxDynamicSharedMemorySize, DYN_BYTES);
    pre_kernel<<<1, 256>>>(ep, nuc);
    fused_kernel<<<GRID, 256, DYN_BYTES>>>(tmap, ep, nuc, b, w, c, fw, fb, pi,
                                           sigma, omega, (float*)d_out);
}